// round 4
// baseline (speedup 1.0000x reference)
#include <cuda_runtime.h>
#include <cuda_bf16.h>
#include <cstdint>

// Problem constants (fixed by the dataset): N=1,000,000 points, C=64 channels, K=64 grid
#define KGRID 64
#define NCELLS (KGRID * KGRID * KGRID)   // 262144
#define NMAX 1000064

// Scratch in __device__ globals (no allocation allowed)
__device__ int g_counts[NCELLS];
__device__ int g_pidx[NMAX];

// ---------------------------------------------------------------------------
// Kernel 1: compute flat voxel index per point + per-cell counts
// ---------------------------------------------------------------------------
__global__ void idx_kernel(const float* __restrict__ points, int n) {
    int i = blockIdx.x * blockDim.x + threadIdx.x;
    if (i >= n) return;
    float x = points[3 * i + 0];
    float y = points[3 * i + 1];
    float z = points[3 * i + 2];
    // match reference: floor((p+1)*k/2), clip to [0, k-1]
    int ix = (int)floorf((x + 1.0f) * (KGRID * 0.5f));
    int iy = (int)floorf((y + 1.0f) * (KGRID * 0.5f));
    int iz = (int)floorf((z + 1.0f) * (KGRID * 0.5f));
    ix = min(max(ix, 0), KGRID - 1);
    iy = min(max(iy, 0), KGRID - 1);
    iz = min(max(iz, 0), KGRID - 1);
    int idx = ix * (KGRID * KGRID) + iy * KGRID + iz;
    g_pidx[i] = idx;
    atomicAdd(&g_counts[idx], 1);
}

// ---------------------------------------------------------------------------
// Kernel 2: scatter-add features into the sums array (d_out) with vector RED.
// 16 threads cooperate on one point: thread q handles float4 chunk q of 16.
// Feature loads are fully coalesced (16 x 16B = one 256B row per point).
// ---------------------------------------------------------------------------
__global__ void scatter_kernel(const float4* __restrict__ feat4,
                               float* __restrict__ out, int n) {
    int gid = blockIdx.x * blockDim.x + threadIdx.x;
    int total = n * 16;
    if (gid >= total) return;
    int pt = gid >> 4;
    int q  = gid & 15;
    int cell = g_pidx[pt];             // broadcast load within the 16-group
    float4 v = feat4[(size_t)pt * 16 + q];
    float* dst = out + (size_t)cell * 64 + q * 4;
    // vector reduction: one L2 atomic op per 16 bytes
    asm volatile("red.global.add.v4.f32 [%0], {%1, %2, %3, %4};"
                 :: "l"(dst), "f"(v.x), "f"(v.y), "f"(v.z), "f"(v.w)
                 : "memory");
}

// ---------------------------------------------------------------------------
// Kernel 3: divide sums by counts (in place), float4-vectorized.
// ---------------------------------------------------------------------------
__global__ void divide_kernel(float4* __restrict__ out) {
    int gid = blockIdx.x * blockDim.x + threadIdx.x;
    const int total = NCELLS * 16;     // 64 floats per cell = 16 float4
    if (gid >= total) return;
    int cell = gid >> 4;
    int c = g_counts[cell];
    float inv = 1.0f / (float)(c > 0 ? c : 1);
    float4 v = out[gid];
    v.x *= inv; v.y *= inv; v.z *= inv; v.w *= inv;
    out[gid] = v;
}

// ---------------------------------------------------------------------------
// Launcher
// inputs: d_in[0] = point_feat (N*64 f32), d_in[1] = points (N*3 f32),
//         d_in[2] = k (int, =64). out: (64,64,64,64) f32
// ---------------------------------------------------------------------------
extern "C" void kernel_launch(void* const* d_in, const int* in_sizes, int n_in,
                              void* d_out, int out_size) {
    const float*  points = (const float*)d_in[1];
    const float4* feat4  = (const float4*)d_in[0];
    float* out = (float*)d_out;

    int n = in_sizes[1] / 3;   // number of points

    // zero the counts scratch and the output (sums accumulator)
    void* counts_ptr = nullptr;
    cudaGetSymbolAddress(&counts_ptr, g_counts);
    cudaMemsetAsync(counts_ptr, 0, NCELLS * sizeof(int), 0);
    cudaMemsetAsync(d_out, 0, (size_t)NCELLS * 64 * sizeof(float), 0);

    const int T = 256;
    idx_kernel<<<(n + T - 1) / T, T>>>(points, n);
    scatter_kernel<<<((size_t)n * 16 + T - 1) / T, T>>>(feat4, out, n);
    divide_kernel<<<(NCELLS * 16 + T - 1) / T, T>>>((float4*)out);
}

// round 5
// speedup vs baseline: 1.2610x; 1.2610x over previous
#include <cuda_runtime.h>
#include <cuda_bf16.h>
#include <cstdint>

// Problem constants (fixed by the dataset): N=1,000,000 points, C=64 channels, K=64 grid
#define KGRID   64
#define NCELLS  (KGRID * KGRID * KGRID)   // 262144
#define NMAX    1000064
#define SCAN_B  512                       // 512 blocks x 512 threads covers 262144

// Scratch in __device__ globals (no allocation allowed)
__device__ int g_counts[NCELLS];
__device__ int g_offsets[NCELLS];   // exclusive-scan result (partial, then final)
__device__ int g_cursor[NCELLS];    // bumped by reorder
__device__ int g_blocksums[SCAN_B];
__device__ int g_pidx[NMAX];
__device__ int g_perm[NMAX];

// ---------------------------------------------------------------------------
// Kernel 1: compute flat voxel index per point + per-cell counts
// ---------------------------------------------------------------------------
__global__ void idx_kernel(const float* __restrict__ points, int n) {
    int i = blockIdx.x * blockDim.x + threadIdx.x;
    if (i >= n) return;
    float x = points[3 * i + 0];
    float y = points[3 * i + 1];
    float z = points[3 * i + 2];
    int ix = (int)floorf((x + 1.0f) * (KGRID * 0.5f));
    int iy = (int)floorf((y + 1.0f) * (KGRID * 0.5f));
    int iz = (int)floorf((z + 1.0f) * (KGRID * 0.5f));
    ix = min(max(ix, 0), KGRID - 1);
    iy = min(max(iy, 0), KGRID - 1);
    iz = min(max(iz, 0), KGRID - 1);
    int idx = ix * (KGRID * KGRID) + iy * KGRID + iz;
    g_pidx[i] = idx;
    atomicAdd(&g_counts[idx], 1);
}

// ---------------------------------------------------------------------------
// Scan stage A: per-block (512-elem) exclusive scan of counts -> g_offsets,
// block totals -> g_blocksums.
// ---------------------------------------------------------------------------
__global__ void scan_block_kernel() {
    __shared__ int s[512];
    int t = threadIdx.x;
    int i = blockIdx.x * 512 + t;
    int v = g_counts[i];
    s[t] = v;
    __syncthreads();
    #pragma unroll
    for (int d = 1; d < 512; d <<= 1) {
        int add = (t >= d) ? s[t - d] : 0;
        __syncthreads();
        s[t] += add;
        __syncthreads();
    }
    int incl = s[t];
    g_offsets[i] = incl - v;                       // exclusive partial
    if (t == 511) g_blocksums[blockIdx.x] = incl;  // block total
}

// ---------------------------------------------------------------------------
// Scan stage B: exclusive scan of the 512 block totals (one block).
// ---------------------------------------------------------------------------
__global__ void scan_top_kernel() {
    __shared__ int s[SCAN_B];
    int t = threadIdx.x;
    int v = g_blocksums[t];
    s[t] = v;
    __syncthreads();
    #pragma unroll
    for (int d = 1; d < SCAN_B; d <<= 1) {
        int add = (t >= d) ? s[t - d] : 0;
        __syncthreads();
        s[t] += add;
        __syncthreads();
    }
    g_blocksums[t] = s[t] - v;   // exclusive
}

// ---------------------------------------------------------------------------
// Scan stage C: add block offsets; also initialize the reorder cursor.
// ---------------------------------------------------------------------------
__global__ void add_offsets_kernel() {
    int i = blockIdx.x * blockDim.x + threadIdx.x;
    if (i >= NCELLS) return;
    int off = g_offsets[i] + g_blocksums[i >> 9];
    g_offsets[i] = off;
    g_cursor[i]  = off;
}

// ---------------------------------------------------------------------------
// Reorder: build permutation grouping point ids by cell.
// ---------------------------------------------------------------------------
__global__ void reorder_kernel(int n) {
    int i = blockIdx.x * blockDim.x + threadIdx.x;
    if (i >= n) return;
    int cell = g_pidx[i];
    int pos = atomicAdd(&g_cursor[cell], 1);
    g_perm[pos] = i;
}

// ---------------------------------------------------------------------------
// Gather + mean: 16 threads per cell, thread q owns float4 lane q.
// Register accumulation, single coalesced output write. No float atomics.
// ---------------------------------------------------------------------------
__global__ void gather_kernel(const float4* __restrict__ feat4,
                              float4* __restrict__ out) {
    int gid = blockIdx.x * blockDim.x + threadIdx.x;   // NCELLS*16 threads
    int cell = gid >> 4;
    int q    = gid & 15;
    int start = g_offsets[cell];
    int cnt   = g_counts[cell];

    float4 acc = make_float4(0.f, 0.f, 0.f, 0.f);
    int j = 0;
    // unroll by 2 for memory-level parallelism on the perm->feat chain
    for (; j + 2 <= cnt; j += 2) {
        int p0 = g_perm[start + j];
        int p1 = g_perm[start + j + 1];
        float4 a = __ldg(&feat4[(size_t)p0 * 16 + q]);
        float4 b = __ldg(&feat4[(size_t)p1 * 16 + q]);
        acc.x += a.x; acc.y += a.y; acc.z += a.z; acc.w += a.w;
        acc.x += b.x; acc.y += b.y; acc.z += b.z; acc.w += b.w;
    }
    if (j < cnt) {
        int p = g_perm[start + j];
        float4 a = __ldg(&feat4[(size_t)p * 16 + q]);
        acc.x += a.x; acc.y += a.y; acc.z += a.z; acc.w += a.w;
    }

    float inv = (cnt > 0) ? (1.0f / (float)cnt) : 1.0f;
    acc.x *= inv; acc.y *= inv; acc.z *= inv; acc.w *= inv;
    out[(size_t)cell * 16 + q] = acc;   // empty cells correctly write 0
}

// ---------------------------------------------------------------------------
// Launcher
// inputs: d_in[0] = point_feat (N*64 f32), d_in[1] = points (N*3 f32),
//         d_in[2] = k (int, =64). out: (64,64,64,64) f32
// ---------------------------------------------------------------------------
extern "C" void kernel_launch(void* const* d_in, const int* in_sizes, int n_in,
                              void* d_out, int out_size) {
    const float*  points = (const float*)d_in[1];
    const float4* feat4  = (const float4*)d_in[0];
    float4* out = (float4*)d_out;

    int n = in_sizes[1] / 3;   // number of points

    // zero only the counts scratch (1 MB); everything else is fully rewritten
    void* counts_ptr = nullptr;
    cudaGetSymbolAddress(&counts_ptr, g_counts);
    cudaMemsetAsync(counts_ptr, 0, NCELLS * sizeof(int), 0);

    const int T = 256;
    idx_kernel<<<(n + T - 1) / T, T>>>(points, n);
    scan_block_kernel<<<SCAN_B, 512>>>();
    scan_top_kernel<<<1, SCAN_B>>>();
    add_offsets_kernel<<<NCELLS / T, T>>>();
    reorder_kernel<<<(n + T - 1) / T, T>>>(n);
    gather_kernel<<<(NCELLS * 16) / T, T>>>(feat4, out);
}